// round 6
// baseline (speedup 1.0000x reference)
#include <cuda_runtime.h>
#include <cuda_bf16.h>
#include <cstdint>

#define NROWS 65536
#define D 64
#define K 1024
#define BLOCK 128
#define NCTAS 512            // 512 CTAs x 128 rows
#define NT_CTAS 308          // bid%5<3 -> tensor path (rows 0..39423)
#define SROW0 (NT_CTAS * BLOCK)
#define BSTRIDE 72           // padded bf16 row stride (conflict-free B loads)
#define TAU 2e-4f

// Per-CTA scratch, fully rewritten every call (no init kernel needed).
__device__ int    g_rcnt[NCTAS];
__device__ int    g_rrows[NCTAS * BLOCK];
__device__ double g_part[NCTAS];
__device__ double g_part2[NCTAS];

__device__ __forceinline__ uint32_t pack_bf16x2(float a, float b) {
    __nv_bfloat162 h = __floats2bfloat162_rn(a, b);
    return *(uint32_t*)&h;
}
__device__ __forceinline__ void mma16816(float& c0, float& c1, float& c2, float& c3,
                                         uint32_t a0, uint32_t a1, uint32_t a2, uint32_t a3,
                                         uint32_t b0, uint32_t b1) {
    asm volatile("mma.sync.aligned.m16n8k16.row.col.f32.bf16.bf16.f32 "
                 "{%0,%1,%2,%3}, {%4,%5,%6,%7}, {%8,%9}, {%0,%1,%2,%3};"
                 : "+f"(c0), "+f"(c1), "+f"(c2), "+f"(c3)
                 : "r"(a0), "r"(a1), "r"(a2), "r"(a3), "r"(b0), "r"(b1));
}

struct MinState { float m1, m2; int idx; };
__device__ __forceinline__ void upd(MinState& s, float d, int e) {
    float mx = fmaxf(s.m1, d);
    bool  lt = d < s.m1;
    s.m1  = fminf(s.m1, d);
    s.idx = lt ? e : s.idx;
    s.m2  = fminf(s.m2, mx);
}
__device__ __forceinline__ void red4(MinState& s) {
    #pragma unroll
    for (int off = 1; off <= 2; off <<= 1) {
        float om1 = __shfl_xor_sync(0xffffffffu, s.m1, off);
        float om2 = __shfl_xor_sync(0xffffffffu, s.m2, off);
        int   oix = __shfl_xor_sync(0xffffffffu, s.idx, off);
        bool take = (om1 < s.m1) || (om1 == s.m1 && oix < s.idx);
        float nm2 = fminf(fminf(s.m2, om2), fmaxf(s.m1, om1));
        s.m1  = fminf(s.m1, om1);
        s.idx = take ? oix : s.idx;
        s.m2  = nm2;
    }
}

__global__ __launch_bounds__(BLOCK)
void vq_main_kernel(const float* __restrict__ z,
                    const float* __restrict__ emb,
                    float* __restrict__ out) {
    __shared__ __align__(16) char sm[40320];
    const int bid  = blockIdx.x;
    const int tid  = threadIdx.x;
    const int warp = tid >> 5;
    const int lane = tid & 31;

    if ((bid % 5) < 3) {
        // ------------------- TENSOR PATH (bf16 MMA + TAU guard) -------------------
        const int ti   = (bid / 5) * 3 + (bid % 5);
        const int wrow = ti * BLOCK + warp * 32;
        __nv_bfloat16* s_b  = (__nv_bfloat16*)sm;           // [256][72] bf16
        float*  s_ee  = (float*)(sm + 36864);               // [256] chunk ||e||^2
        float*  s_m1  = (float*)(sm + 37888);
        float*  s_m2  = (float*)(sm + 38400);
        int*    s_ix  = (int*)(sm + 38912);
        int*    s_rl  = (int*)(sm + 39424);
        int*    s_rc  = (int*)(sm + 39936);
        double* s_red = (double*)(sm + 39944);

        if (tid == 0) *s_rc = 0;

        const int g = lane >> 2, t = lane & 3;

        // A fragments: z rows bf16, register-resident all kernel.
        uint32_t A[2][4][4];
        #pragma unroll
        for (int tl = 0; tl < 2; ++tl) {
            const float* r0 = z + (size_t)(wrow + tl * 16 + g) * D;
            const float* r1 = r0 + 8 * D;
            #pragma unroll
            for (int ks = 0; ks < 4; ++ks) {
                int kb = ks * 16 + 2 * t;
                float2 u0 = *(const float2*)(r0 + kb);
                float2 u1 = *(const float2*)(r1 + kb);
                float2 u2 = *(const float2*)(r0 + kb + 8);
                float2 u3 = *(const float2*)(r1 + kb + 8);
                A[tl][ks][0] = pack_bf16x2(u0.x, u0.y);
                A[tl][ks][1] = pack_bf16x2(u1.x, u1.y);
                A[tl][ks][2] = pack_bf16x2(u2.x, u2.y);
                A[tl][ks][3] = pack_bf16x2(u3.x, u3.y);
            }
        }

        MinState U0 = {3.4e38f, 3.4e38f, 0}, L0 = U0, U1 = U0, L1 = U0;

        for (int ch = 0; ch < 4; ++ch) {
            __syncthreads();
            // Stage 256 entries: fp32 -> bf16 + exact fp32 ||e||^2, 2 entries/thread.
            #pragma unroll
            for (int e2 = 0; e2 < 2; ++e2) {
                int ent = tid * 2 + e2;
                const float4* src = (const float4*)(emb + (size_t)(ch * 256 + ent) * D);
                uint4* dst = (uint4*)(s_b + ent * BSTRIDE);
                float s = 0.f;
                #pragma unroll
                for (int j = 0; j < 8; ++j) {
                    float4 v0 = src[2 * j], v1 = src[2 * j + 1];
                    s += v0.x * v0.x; s += v0.y * v0.y; s += v0.z * v0.z; s += v0.w * v0.w;
                    s += v1.x * v1.x; s += v1.y * v1.y; s += v1.z * v1.z; s += v1.w * v1.w;
                    uint4 q;
                    q.x = pack_bf16x2(v0.x, v0.y); q.y = pack_bf16x2(v0.z, v0.w);
                    q.z = pack_bf16x2(v1.x, v1.y); q.w = pack_bf16x2(v1.z, v1.w);
                    dst[j] = q;
                }
                s_ee[ent] = s;
            }
            __syncthreads();

            for (int nt = 0; nt < 32; ++nt) {
                const int nbl = nt * 8;
                float c00 = 0.f, c01 = 0.f, c02 = 0.f, c03 = 0.f;
                float c10 = 0.f, c11 = 0.f, c12 = 0.f, c13 = 0.f;
                const __nv_bfloat16* brow = s_b + (nbl + g) * BSTRIDE + 2 * t;
                #pragma unroll
                for (int ks = 0; ks < 4; ++ks) {
                    uint32_t b0 = *(const uint32_t*)(brow + ks * 16);
                    uint32_t b1 = *(const uint32_t*)(brow + ks * 16 + 8);
                    mma16816(c00, c01, c02, c03,
                             A[0][ks][0], A[0][ks][1], A[0][ks][2], A[0][ks][3], b0, b1);
                    mma16816(c10, c11, c12, c13,
                             A[1][ks][0], A[1][ks][1], A[1][ks][2], A[1][ks][3], b0, b1);
                }
                float2 ee = *(const float2*)(s_ee + nbl + 2 * t);
                int e0 = ch * 256 + nbl + 2 * t, e1 = e0 + 1;
                upd(U0, fmaf(-2.f, c00, ee.x), e0);
                upd(U0, fmaf(-2.f, c01, ee.y), e1);
                upd(L0, fmaf(-2.f, c02, ee.x), e0);
                upd(L0, fmaf(-2.f, c03, ee.y), e1);
                upd(U1, fmaf(-2.f, c10, ee.x), e0);
                upd(U1, fmaf(-2.f, c11, ee.y), e1);
                upd(L1, fmaf(-2.f, c12, ee.x), e0);
                upd(L1, fmaf(-2.f, c13, ee.y), e1);
            }
        }

        red4(U0); red4(L0); red4(U1); red4(L1);
        if (t == 0) {
            int lr = warp * 32 + g;
            s_m1[lr]      = U0.m1; s_m2[lr]      = U0.m2; s_ix[lr]      = U0.idx;
            s_m1[lr + 8]  = L0.m1; s_m2[lr + 8]  = L0.m2; s_ix[lr + 8]  = L0.idx;
            s_m1[lr + 16] = U1.m1; s_m2[lr + 16] = U1.m2; s_ix[lr + 16] = U1.idx;
            s_m1[lr + 24] = L1.m1; s_m2[lr + 24] = L1.m2; s_ix[lr + 24] = L1.idx;
        }
        __syncthreads();

        const int row = ti * BLOCK + tid;
        float m1 = s_m1[tid], m2 = s_m2[tid];
        int   idx1 = s_ix[tid];
        const float4* zp = (const float4*)z + (size_t)row * 16;

        double lacc = 0.0;
        if (m2 - m1 < TAU) {
            int p = atomicAdd(s_rc, 1);
            s_rl[p] = row;
        } else {
            const float4* eb = (const float4*)emb + (size_t)idx1 * 16;
            float4* op = (float4*)out + (size_t)row * 16;
            #pragma unroll
            for (int j = 0; j < 16; ++j) {
                float4 q = eb[j]; float4 zv = zp[j];
                op[j] = q;
                float dx = q.x - zv.x, dy = q.y - zv.y;
                float dz = q.z - zv.z, dw = q.w - zv.w;
                lacc += (double)dx * dx + (double)dy * dy
                      + (double)dz * dz + (double)dw * dw;
            }
        }
        #pragma unroll
        for (int off = 16; off; off >>= 1)
            lacc += __shfl_down_sync(0xffffffffu, lacc, off);
        if (lane == 0) s_red[warp] = lacc;
        __syncthreads();
        int cnt = *s_rc;
        if (tid < cnt) g_rrows[bid * BLOCK + tid] = s_rl[tid];
        if (tid == 0) {
            g_rcnt[bid] = cnt;
            g_part[bid] = s_red[0] + s_red[1] + s_red[2] + s_red[3];
        }
    } else {
        // ------------------- SCALAR PATH (exact fp32, R1 arithmetic) -------------------
        const int si  = (bid / 5) * 2 + (bid % 5) - 3;
        const int row = SROW0 + si * BLOCK + tid;
        float4* s_emb = (float4*)sm;                        // [128*16]
        float*  s_ee2 = (float*)(sm + 32768);               // [128]
        double* s_red = (double*)(sm + 33280);

        float4 zr[16];
        const float4* zp = (const float4*)z + (size_t)row * 16;
        #pragma unroll
        for (int j = 0; j < 16; ++j) zr[j] = zp[j];

        float zz = 0.f;
        #pragma unroll
        for (int j = 0; j < 16; ++j) {
            zz += zr[j].x * zr[j].x; zz += zr[j].y * zr[j].y;
            zz += zr[j].z * zr[j].z; zz += zr[j].w * zr[j].w;
        }

        float dmin = 3.4e38f;
        int   best = 0;

        for (int t8 = 0; t8 < 8; ++t8) {
            __syncthreads();
            for (int f = tid; f < 128 * 16; f += BLOCK)
                s_emb[f] = ((const float4*)emb)[(size_t)t8 * 128 * 16 + f];
            {   // exact ||e||^2 from global, R1 pre-kernel order
                const float4* e = (const float4*)emb + (size_t)(t8 * 128 + tid) * 16;
                float s = 0.f;
                #pragma unroll
                for (int j = 0; j < 16; ++j) {
                    float4 v = e[j];
                    s += v.x * v.x; s += v.y * v.y; s += v.z * v.z; s += v.w * v.w;
                }
                s_ee2[tid] = s;
            }
            __syncthreads();
            for (int kk = 0; kk < 128; ++kk) {
                const float4* e = &s_emb[kk * 16];
                float ze = 0.f;
                #pragma unroll
                for (int j = 0; j < 16; ++j) {
                    float4 ev = e[j];
                    ze += zr[j].x * ev.x; ze += zr[j].y * ev.y;
                    ze += zr[j].z * ev.z; ze += zr[j].w * ev.w;
                }
                float d = (zz - 2.0f * ze) + s_ee2[kk];
                if (d < dmin) { dmin = d; best = t8 * 128 + kk; }
            }
        }

        double lacc = 0.0;
        const float4* eb = (const float4*)emb + (size_t)best * 16;
        float4* op = (float4*)out + (size_t)row * 16;
        #pragma unroll
        for (int j = 0; j < 16; ++j) {
            float4 q = eb[j];
            op[j] = q;
            float dx = q.x - zr[j].x, dy = q.y - zr[j].y;
            float dz = q.z - zr[j].z, dw = q.w - zr[j].w;
            lacc += (double)dx * dx + (double)dy * dy
                  + (double)dz * dz + (double)dw * dw;
        }
        #pragma unroll
        for (int off = 16; off; off >>= 1)
            lacc += __shfl_down_sync(0xffffffffu, lacc, off);
        if (lane == 0) s_red[warp] = lacc;
        __syncthreads();
        if (tid == 0) {
            g_rcnt[bid] = 0;
            g_part[bid] = s_red[0] + s_red[1] + s_red[2] + s_red[3];
        }
    }
}

// Exact fp32 rescan for near-tie tensor rows. Block b serves main-CTA b's list.
__global__ __launch_bounds__(256)
void vq_rescore_kernel(const float* __restrict__ z,
                       const float* __restrict__ emb,
                       float* __restrict__ out) {
    __shared__ float s_emb[128 * 69];
    __shared__ float s_eer[128];
    __shared__ float s_zrow[8 * 64];
    __shared__ int   s_rows[8];
    __shared__ double s_red[8];

    const int b = blockIdx.x;
    const int n = g_rcnt[b];
    const int tid = threadIdx.x;
    const int w = tid >> 5, l = tid & 31;

    if (n == 0) { if (tid == 0) g_part2[b] = 0.0; return; }

    double wacc = 0.0;
    for (int base = 0; base < n; base += 8) {
        __syncthreads();
        if (tid < 8)
            s_rows[tid] = (base + tid < n) ? g_rrows[b * BLOCK + base + tid] : -1;
        __syncthreads();
        if (tid < 8 * 16) {
            int rw = tid >> 4, j = tid & 15;
            int r = s_rows[rw];
            if (r >= 0)
                *(float4*)(s_zrow + rw * 64 + j * 4) = ((const float4*)z)[(size_t)r * 16 + j];
        }
        __syncthreads();

        int myrow = s_rows[w];
        float zz = 0.f;
        if (myrow >= 0)
            for (int i = 0; i < 64; ++i) { float v = s_zrow[w * 64 + i]; zz += v * v; }

        float dmin = 3.4e38f;
        int   bestk = 0;

        for (int tt = 0; tt < 8; ++tt) {
            __syncthreads();
            for (int f = tid; f < 128 * 16; f += 256) {
                int e = f >> 4, j = f & 15;
                float4 v = ((const float4*)emb)[(size_t)(tt * 128 + e) * 16 + j];
                float* dst = s_emb + e * 69 + j * 4;
                dst[0] = v.x; dst[1] = v.y; dst[2] = v.z; dst[3] = v.w;
            }
            if (tid < 128) {
                const float4* e = (const float4*)emb + (size_t)(tt * 128 + tid) * 16;
                float s = 0.f;
                #pragma unroll
                for (int j = 0; j < 16; ++j) {
                    float4 v = e[j];
                    s += v.x * v.x; s += v.y * v.y; s += v.z * v.z; s += v.w * v.w;
                }
                s_eer[tid] = s;
            }
            __syncthreads();
            if (myrow >= 0) {
                #pragma unroll
                for (int s = 0; s < 4; ++s) {
                    int el = s * 32 + l;
                    const float* e = s_emb + el * 69;
                    float ze = 0.f;
                    for (int i = 0; i < 64; ++i) ze += s_zrow[w * 64 + i] * e[i];
                    int ge = tt * 128 + el;
                    float d = (zz - 2.0f * ze) + s_eer[el];
                    if (d < dmin) { dmin = d; bestk = ge; }
                }
            }
        }

        #pragma unroll
        for (int off = 16; off; off >>= 1) {
            float od = __shfl_down_sync(0xffffffffu, dmin, off);
            int   oi = __shfl_down_sync(0xffffffffu, bestk, off);
            if (od < dmin || (od == dmin && oi < bestk)) { dmin = od; bestk = oi; }
        }

        if (myrow >= 0 && l == 0) {
            const float4* eb = (const float4*)emb + (size_t)bestk * 16;
            float4* op = (float4*)out + (size_t)myrow * 16;
            for (int j = 0; j < 16; ++j) {
                float4 q = eb[j];
                float zx = s_zrow[w * 64 + j * 4 + 0];
                float zy = s_zrow[w * 64 + j * 4 + 1];
                float zzv = s_zrow[w * 64 + j * 4 + 2];
                float zw = s_zrow[w * 64 + j * 4 + 3];
                op[j] = q;
                float dx = q.x - zx, dy = q.y - zy, dz = q.z - zzv, dw = q.w - zw;
                wacc += (double)dx * dx + (double)dy * dy
                      + (double)dz * dz + (double)dw * dw;
            }
        }
    }
    __syncthreads();
    if (l == 0) s_red[w] = wacc;
    __syncthreads();
    if (tid == 0) {
        double s = 0.0;
        #pragma unroll
        for (int i = 0; i < 8; ++i) s += s_red[i];
        g_part2[b] = s;
    }
}

__global__ __launch_bounds__(512)
void vq_fin_kernel(float* __restrict__ out, int out_size) {
    __shared__ double s_red[16];
    int tid = threadIdx.x;
    double v = g_part[tid] + g_part2[tid];
    #pragma unroll
    for (int off = 16; off; off >>= 1)
        v += __shfl_down_sync(0xffffffffu, v, off);
    if ((tid & 31) == 0) s_red[tid >> 5] = v;
    __syncthreads();
    if (tid == 0) {
        double s = 0.0;
        #pragma unroll
        for (int i = 0; i < 16; ++i) s += s_red[i];
        if (out_size > NROWS * D)
            out[NROWS * D] = (float)(1.25 * s / (double)((long long)NROWS * D));
    }
}

extern "C" void kernel_launch(void* const* d_in, const int* in_sizes, int n_in,
                              void* d_out, int out_size) {
    const float* z   = (const float*)d_in[0];
    const float* emb = (const float*)d_in[1];
    if (n_in >= 2 && in_sizes[0] == K * D && in_sizes[1] == NROWS * D) {
        z   = (const float*)d_in[1];
        emb = (const float*)d_in[0];
    }
    float* out = (float*)d_out;

    vq_main_kernel<<<NCTAS, BLOCK>>>(z, emb, out);
    vq_rescore_kernel<<<NCTAS, 256>>>(z, emb, out);
    vq_fin_kernel<<<1, 512>>>(out, out_size);
}

// round 7
// speedup vs baseline: 2.0554x; 2.0554x over previous
#include <cuda_runtime.h>
#include <cuda_bf16.h>
#include <cstdint>

#define NROWS 65536
#define D 64
#define K 1024
#define BLOCK 128          // 4 warps; 32 rows/warp; 128 rows/CTA; 512 CTAs
#define CH 128             // codebook entries per smem chunk
#define NCH (K / CH)       // 8
#define BSTRIDE 72         // padded bf16 row stride (conflict-free B loads)
#define TAU 2e-4f
#define RW 8

// Static scratch (no allocations allowed).
__device__ __nv_bfloat16 g_emb_bf16[K * D];
__device__ float  g_ee[K];
__device__ double g_acc;
__device__ int    g_rescore_n;
__device__ int    g_rescore_rows[NROWS];

__device__ __forceinline__ uint32_t pack_bf16x2(float a, float b) {
    __nv_bfloat162 h = __floats2bfloat162_rn(a, b);
    return *(uint32_t*)&h;
}
__device__ __forceinline__ void mma16816(float& c0, float& c1, float& c2, float& c3,
                                         uint32_t a0, uint32_t a1, uint32_t a2, uint32_t a3,
                                         uint32_t b0, uint32_t b1) {
    asm volatile("mma.sync.aligned.m16n8k16.row.col.f32.bf16.bf16.f32 "
                 "{%0,%1,%2,%3}, {%4,%5,%6,%7}, {%8,%9}, {%0,%1,%2,%3};"
                 : "+f"(c0), "+f"(c1), "+f"(c2), "+f"(c3)
                 : "r"(a0), "r"(a1), "r"(a2), "r"(a3), "r"(b0), "r"(b1));
}

struct MinState { float m1, m2; int idx; };
__device__ __forceinline__ void upd(MinState& s, float d, int e) {
    float mx = fmaxf(s.m1, d);
    bool  lt = d < s.m1;
    s.m1  = fminf(s.m1, d);
    s.idx = lt ? e : s.idx;
    s.m2  = fminf(s.m2, mx);
}
__device__ __forceinline__ void red4(MinState& s) {
    #pragma unroll
    for (int off = 1; off <= 2; off <<= 1) {
        float om1 = __shfl_xor_sync(0xffffffffu, s.m1, off);
        float om2 = __shfl_xor_sync(0xffffffffu, s.m2, off);
        int   oix = __shfl_xor_sync(0xffffffffu, s.idx, off);
        bool take = (om1 < s.m1) || (om1 == s.m1 && oix < s.idx);
        float nm2 = fminf(fminf(s.m2, om2), fmaxf(s.m1, om1));
        s.m1  = fminf(s.m1, om1);
        s.idx = take ? oix : s.idx;
        s.m2  = nm2;
    }
}

__global__ void vq_pre_kernel(const float* __restrict__ emb) {
    int k = blockIdx.x * blockDim.x + threadIdx.x;
    if (k == 0) { g_acc = 0.0; g_rescore_n = 0; }
    if (k < K) {
        const float4* e = (const float4*)(emb + k * D);
        float s = 0.f;
        #pragma unroll
        for (int j = 0; j < 16; ++j) {
            float4 v = e[j];
            s += v.x * v.x; s += v.y * v.y; s += v.z * v.z; s += v.w * v.w;
            *(uint32_t*)(g_emb_bf16 + k * D + j * 4)     = pack_bf16x2(v.x, v.y);
            *(uint32_t*)(g_emb_bf16 + k * D + j * 4 + 2) = pack_bf16x2(v.z, v.w);
        }
        g_ee[k] = s;
    }
}

__global__ __launch_bounds__(BLOCK, 6)
void vq_main_kernel(const float* __restrict__ z,
                    const float* __restrict__ emb,
                    float* __restrict__ out) {
    __shared__ __nv_bfloat16 s_b[CH * BSTRIDE];    // 18 KB codebook chunk
    __shared__ float  s_ee[K];                     // 4 KB, loaded once
    __shared__ float  s_m1[BLOCK], s_m2[BLOCK];
    __shared__ int    s_ix[BLOCK];
    __shared__ double s_red[BLOCK / 32];

    const int tid   = threadIdx.x;
    const int warp  = tid >> 5;
    const int lane  = tid & 31;
    const int g     = lane >> 2;
    const int t     = lane & 3;
    const int rbase = blockIdx.x * BLOCK;
    const int wrow  = rbase + warp * 32;

    #pragma unroll
    for (int i = 0; i < K / BLOCK; ++i)
        s_ee[i * BLOCK + tid] = g_ee[i * BLOCK + tid];

    // A fragments: z rows bf16, register-resident for whole kernel.
    uint32_t A[2][4][4];
    #pragma unroll
    for (int tl = 0; tl < 2; ++tl) {
        const float* r0 = z + (size_t)(wrow + tl * 16 + g) * D;
        const float* r1 = r0 + 8 * D;
        #pragma unroll
        for (int ks = 0; ks < 4; ++ks) {
            int kb = ks * 16 + 2 * t;
            float2 u0 = *(const float2*)(r0 + kb);
            float2 u1 = *(const float2*)(r1 + kb);
            float2 u2 = *(const float2*)(r0 + kb + 8);
            float2 u3 = *(const float2*)(r1 + kb + 8);
            A[tl][ks][0] = pack_bf16x2(u0.x, u0.y);
            A[tl][ks][1] = pack_bf16x2(u1.x, u1.y);
            A[tl][ks][2] = pack_bf16x2(u2.x, u2.y);
            A[tl][ks][3] = pack_bf16x2(u3.x, u3.y);
        }
    }

    MinState U0 = {3.4e38f, 3.4e38f, 0}, L0 = U0, U1 = U0, L1 = U0;

    for (int ch = 0; ch < NCH; ++ch) {
        __syncthreads();
        // Stage 128 codebook entries: 1 per thread, 8 x 16B.
        {
            const uint4* src = (const uint4*)g_emb_bf16 + (size_t)(ch * CH + tid) * 8;
            uint4* dst = (uint4*)(s_b + tid * BSTRIDE);
            #pragma unroll
            for (int i = 0; i < 8; ++i) dst[i] = src[i];
        }
        __syncthreads();

        for (int nt = 0; nt < CH / 8; ++nt) {
            const int nbl = nt * 8;
            const int nb  = ch * CH + nbl;
            float c00 = 0.f, c01 = 0.f, c02 = 0.f, c03 = 0.f;
            float c10 = 0.f, c11 = 0.f, c12 = 0.f, c13 = 0.f;
            const __nv_bfloat16* brow = s_b + (nbl + g) * BSTRIDE + 2 * t;
            #pragma unroll
            for (int ks = 0; ks < 4; ++ks) {
                uint32_t b0 = *(const uint32_t*)(brow + ks * 16);
                uint32_t b1 = *(const uint32_t*)(brow + ks * 16 + 8);
                mma16816(c00, c01, c02, c03,
                         A[0][ks][0], A[0][ks][1], A[0][ks][2], A[0][ks][3], b0, b1);
                mma16816(c10, c11, c12, c13,
                         A[1][ks][0], A[1][ks][1], A[1][ks][2], A[1][ks][3], b0, b1);
            }
            float2 ee = *(const float2*)(s_ee + nb + 2 * t);
            int e0 = nb + 2 * t, e1 = e0 + 1;
            upd(U0, fmaf(-2.f, c00, ee.x), e0);
            upd(U0, fmaf(-2.f, c01, ee.y), e1);
            upd(L0, fmaf(-2.f, c02, ee.x), e0);
            upd(L0, fmaf(-2.f, c03, ee.y), e1);
            upd(U1, fmaf(-2.f, c10, ee.x), e0);
            upd(U1, fmaf(-2.f, c11, ee.y), e1);
            upd(L1, fmaf(-2.f, c12, ee.x), e0);
            upd(L1, fmaf(-2.f, c13, ee.y), e1);
        }
    }

    red4(U0); red4(L0); red4(U1); red4(L1);
    if (t == 0) {
        int lr = warp * 32 + g;
        s_m1[lr]      = U0.m1; s_m2[lr]      = U0.m2; s_ix[lr]      = U0.idx;
        s_m1[lr + 8]  = L0.m1; s_m2[lr + 8]  = L0.m2; s_ix[lr + 8]  = L0.idx;
        s_m1[lr + 16] = U1.m1; s_m2[lr + 16] = U1.m2; s_ix[lr + 16] = U1.idx;
        s_m1[lr + 24] = L1.m1; s_m2[lr + 24] = L1.m2; s_ix[lr + 24] = L1.idx;
    }
    __syncthreads();

    // Epilogue: one thread per row.
    const int row = rbase + tid;
    float m1 = s_m1[tid], m2 = s_m2[tid];
    int   idx1 = s_ix[tid];
    const float4* zp = (const float4*)z + (size_t)row * 16;

    double lacc = 0.0;
    if (m2 - m1 < TAU) {
        int pos = atomicAdd(&g_rescore_n, 1);
        g_rescore_rows[pos] = row;
    } else {
        const float4* eb = (const float4*)emb + (size_t)idx1 * 16;
        float4* op = (float4*)out + (size_t)row * 16;
        #pragma unroll
        for (int j = 0; j < 16; ++j) {
            float4 q = eb[j];
            float4 zv = zp[j];
            op[j] = q;
            float dx = q.x - zv.x, dy = q.y - zv.y;
            float dz = q.z - zv.z, dw = q.w - zv.w;
            lacc += (double)dx * dx + (double)dy * dy
                  + (double)dz * dz + (double)dw * dw;
        }
    }
    #pragma unroll
    for (int off = 16; off; off >>= 1)
        lacc += __shfl_down_sync(0xffffffffu, lacc, off);
    if (lane == 0) s_red[warp] = lacc;
    __syncthreads();
    if (tid == 0)
        atomicAdd(&g_acc, s_red[0] + s_red[1] + s_red[2] + s_red[3]);
}

// Exact fp32 full rescan for near-tie rows (R1 arithmetic order; matched ref).
__global__ __launch_bounds__(256)
void vq_rescore_kernel(const float* __restrict__ z,
                       const float* __restrict__ emb,
                       float* __restrict__ out) {
    __shared__ float s_emb[128 * 69];
    __shared__ float s_zrow[RW * 64];
    __shared__ int   s_rows[RW];

    int nre  = g_rescore_n;
    int base = blockIdx.x * RW;
    if (base >= nre) return;

    int tid = threadIdx.x;
    int w = tid >> 5, l = tid & 31;

    if (tid < RW)
        s_rows[tid] = (base + tid < nre) ? g_rescore_rows[base + tid] : -1;
    __syncthreads();

    if (tid < RW * 16) {
        int rw = tid >> 4, j = tid & 15;
        int r = s_rows[rw];
        if (r >= 0)
            *(float4*)(s_zrow + rw * 64 + j * 4) = ((const float4*)z)[(size_t)r * 16 + j];
    }
    __syncthreads();

    int myrow = s_rows[w];

    float zz = 0.f;
    if (myrow >= 0)
        for (int i = 0; i < 64; ++i) { float v = s_zrow[w * 64 + i]; zz += v * v; }

    float dmin = 3.4e38f;
    int   best = 0;

    for (int tt = 0; tt < K / 128; ++tt) {
        __syncthreads();
        for (int f = tid; f < 128 * 16; f += 256) {
            int e = f >> 4, j = f & 15;
            float4 v = ((const float4*)emb)[(size_t)(tt * 128 + e) * 16 + j];
            float* dst = s_emb + e * 69 + j * 4;
            dst[0] = v.x; dst[1] = v.y; dst[2] = v.z; dst[3] = v.w;
        }
        __syncthreads();
        if (myrow >= 0) {
            #pragma unroll
            for (int s = 0; s < 4; ++s) {
                int el = s * 32 + l;
                const float* e = s_emb + el * 69;
                float ze = 0.f;
                for (int i = 0; i < 64; ++i) ze += s_zrow[w * 64 + i] * e[i];
                int ge = tt * 128 + el;
                float d = (zz - 2.0f * ze) + g_ee[ge];
                if (d < dmin) { dmin = d; best = ge; }
            }
        }
    }

    #pragma unroll
    for (int off = 16; off; off >>= 1) {
        float od = __shfl_down_sync(0xffffffffu, dmin, off);
        int   oi = __shfl_down_sync(0xffffffffu, best, off);
        if (od < dmin || (od == dmin && oi < best)) { dmin = od; best = oi; }
    }

    if (myrow >= 0 && l == 0) {
        const float4* eb = (const float4*)emb + (size_t)best * 16;
        float4* op = (float4*)out + (size_t)myrow * 16;
        double lacc = 0.0;
        for (int j = 0; j < 16; ++j) {
            float4 q = eb[j];
            float zx = s_zrow[w * 64 + j * 4 + 0];
            float zy = s_zrow[w * 64 + j * 4 + 1];
            float zzv = s_zrow[w * 64 + j * 4 + 2];
            float zw = s_zrow[w * 64 + j * 4 + 3];
            op[j] = q;
            float dx = q.x - zx, dy = q.y - zy, dz = q.z - zzv, dw = q.w - zw;
            lacc += (double)dx * dx + (double)dy * dy
                  + (double)dz * dz + (double)dw * dw;
        }
        atomicAdd(&g_acc, lacc);
    }
}

__global__ void vq_fin_kernel(float* __restrict__ out, int out_size) {
    if (out_size > NROWS * D) {
        out[NROWS * D] = (float)(1.25 * g_acc / (double)((long long)NROWS * D));
    }
}

extern "C" void kernel_launch(void* const* d_in, const int* in_sizes, int n_in,
                              void* d_out, int out_size) {
    const float* z   = (const float*)d_in[0];
    const float* emb = (const float*)d_in[1];
    if (n_in >= 2 && in_sizes[0] == K * D && in_sizes[1] == NROWS * D) {
        z   = (const float*)d_in[1];
        emb = (const float*)d_in[0];
    }
    float* out = (float*)d_out;

    vq_pre_kernel<<<8, 128>>>(emb);
    vq_main_kernel<<<NROWS / BLOCK, BLOCK>>>(z, emb, out);
    vq_rescore_kernel<<<NROWS / RW, 256>>>(z, emb, out);
    vq_fin_kernel<<<1, 1>>>(out, out_size);
}